// round 15
// baseline (speedup 1.0000x reference)
#include <cuda_runtime.h>
#include <cuda_fp16.h>
#include <cstdint>

// Problem shapes (fixed by the dataset)
#define BATCH 8
#define LQ    1024
#define LK    1024
#define DIM   512
#define CH    512
#define KTOT  1536   // 3*CH

// ---------------------------------------------------------------------------
// Scratch (device globals). Referenced ONLY from device code (host-side
// &g_xxx yields the shadow symbol: the round-3/4 bug).
// ---------------------------------------------------------------------------
__device__ __half g_qh[BATCH * LQ * DIM];
__device__ __half g_kh[BATCH * LK * CH];
__device__ __half g_Wh[DIM * KTOT];              // Wop[d][w*CH+c] = W[d, c*3+w]
__device__ __half g_Uh[BATCH * LK * DIM];
__device__ float g_qb[BATCH * LQ];
__device__ float g_t0[BATCH * LK];               // per-row dots for bbj conv
__device__ float g_t1[BATCH * LK];
__device__ float g_t2[BATCH * LK];
__device__ unsigned int g_tileCtr;               // persistent-gemmB work counter

// ---------------------------------------------------------------------------
// PTX helpers
// ---------------------------------------------------------------------------
__device__ __forceinline__ void mma16816(float* c,
                                         uint32_t a0, uint32_t a1, uint32_t a2, uint32_t a3,
                                         uint32_t b0, uint32_t b1) {
    asm volatile(
        "mma.sync.aligned.m16n8k16.row.col.f32.f16.f16.f32 "
        "{%0,%1,%2,%3}, {%4,%5,%6,%7}, {%8,%9}, {%0,%1,%2,%3};"
        : "+f"(c[0]), "+f"(c[1]), "+f"(c[2]), "+f"(c[3])
        : "r"(a0), "r"(a1), "r"(a2), "r"(a3), "r"(b0), "r"(b1));
}

__device__ __forceinline__ void ldm4(uint32_t& r0, uint32_t& r1, uint32_t& r2, uint32_t& r3,
                                     uint32_t a) {
    asm volatile("ldmatrix.sync.aligned.m8n8.x4.shared.b16 {%0,%1,%2,%3}, [%4];"
                 : "=r"(r0), "=r"(r1), "=r"(r2), "=r"(r3) : "r"(a));
}

__device__ __forceinline__ uint32_t smem_u32(const void* p) {
    uint32_t a;
    asm("{ .reg .u64 t; cvta.to.shared.u64 t, %1; cvt.u32.u64 %0, t; }" : "=r"(a) : "l"(p));
    return a;
}

__device__ __forceinline__ void cpa16(uint32_t dst, const void* src, int srcsz) {
    asm volatile("cp.async.cg.shared.global [%0], [%1], 16, %2;"
                 :: "r"(dst), "l"(src), "r"(srcsz) : "memory");
}
#define CP_COMMIT() asm volatile("cp.async.commit_group;" ::: "memory")
#define CP_WAIT1()  asm volatile("cp.async.wait_group 1;" ::: "memory")
#define CP_WAIT0()  asm volatile("cp.async.wait_group 0;" ::: "memory")

// smem tile: 128 rows x 64 bytes (32 fp16), XOR-swizzled:
//   phys = row*64 + (kb ^ (((row>>1)&3)<<4))
__device__ __forceinline__ uint32_t sw_off(int row, int kb) {
    return (uint32_t)(row * 64 + (kb ^ (((row >> 1) & 3) << 4)));
}

__device__ __forceinline__ uint32_t pack_h16(float a, float b) {
    return (uint32_t)__half_as_ushort(__float2half_rn(a)) |
           ((uint32_t)__half_as_ushort(__float2half_rn(b)) << 16);
}

// ---------------------------------------------------------------------------
// Fused preamble (round-13 measured-best form): 2 rows per warp in q/k
// paths, coalesced W repack. Also resets the gemmB tile counter.
//   blocks [0,512):     q -> fp16 + qb row dots
//   blocks [512,1024):  k -> fp16 + t0/t1/t2 row dots
//   blocks [1024,2048): W repack -> fp16 (thread per (d,c) triple)
// ---------------------------------------------------------------------------
__global__ void preamble_kernel(const float* __restrict__ q,
                                const float* __restrict__ k,
                                const float* __restrict__ W,
                                const float* __restrict__ bk,
                                const float* __restrict__ Wb,
                                const float* __restrict__ bb) {
    int bid = blockIdx.x;
    int tid = threadIdx.x;
    if (bid == 0 && tid == 0) g_tileCtr = 0;      // reset persistent counter
    if (bid < 512) {
        int wpair = (bid * 256 + tid) >> 5;         // 0..4095 -> rows 2w, 2w+1
        int lane  = tid & 31;
        int r0 = 2 * wpair, r1 = r0 + 1;
        const float4* q0  = reinterpret_cast<const float4*>(q) + (size_t)r0 * 128;
        const float4* q1  = reinterpret_cast<const float4*>(q) + (size_t)r1 * 128;
        const float4* wb4 = reinterpret_cast<const float4*>(Wb);
        float s0 = 0.f, s1 = 0.f;
        #pragma unroll
        for (int v = 0; v < 4; ++v) {
            int idx = lane + 32 * v;
            float4 x0 = q0[idx];
            float4 x1 = q1[idx];
            float4 wv = wb4[idx];
            s0 += x0.x * wv.x + x0.y * wv.y + x0.z * wv.z + x0.w * wv.w;
            s1 += x1.x * wv.x + x1.y * wv.y + x1.z * wv.z + x1.w * wv.w;
            reinterpret_cast<uint2*>(g_qh)[(size_t)r0 * 128 + idx] =
                make_uint2(pack_h16(x0.x, x0.y), pack_h16(x0.z, x0.w));
            reinterpret_cast<uint2*>(g_qh)[(size_t)r1 * 128 + idx] =
                make_uint2(pack_h16(x1.x, x1.y), pack_h16(x1.z, x1.w));
        }
        #pragma unroll
        for (int o = 16; o; o >>= 1) {
            s0 += __shfl_down_sync(0xFFFFFFFFu, s0, o);
            s1 += __shfl_down_sync(0xFFFFFFFFu, s1, o);
        }
        if (lane == 0) {
            float b0v = bb[0];
            g_qb[r0] = s0 + b0v;
            g_qb[r1] = s1 + b0v;
        }
    } else if (bid < 1024) {
        int wpair = ((bid - 512) * 256 + tid) >> 5;
        int lane  = tid & 31;
        int r0 = 2 * wpair, r1 = r0 + 1;
        const float4* k0  = reinterpret_cast<const float4*>(k) + (size_t)r0 * 128;
        const float4* k1  = reinterpret_cast<const float4*>(k) + (size_t)r1 * 128;
        const float4* bk4 = reinterpret_cast<const float4*>(bk);
        float a0 = 0.f, a1 = 0.f, a2 = 0.f;      // row r0 dots
        float c0 = 0.f, c1 = 0.f, c2 = 0.f;      // row r1 dots
        #pragma unroll
        for (int v = 0; v < 4; ++v) {
            int idx = lane + 32 * v;              // float4 slot; c0 = 4*idx
            float4 x0 = k0[idx];
            float4 x1 = k1[idx];
            float4 f0 = bk4[3 * idx + 0];
            float4 f1 = bk4[3 * idx + 1];
            float4 f2 = bk4[3 * idx + 2];
            a0 += x0.x * f0.x + x0.y * f0.w + x0.z * f1.z + x0.w * f2.y;
            a1 += x0.x * f0.y + x0.y * f1.x + x0.z * f1.w + x0.w * f2.z;
            a2 += x0.x * f0.z + x0.y * f1.y + x0.z * f2.x + x0.w * f2.w;
            c0 += x1.x * f0.x + x1.y * f0.w + x1.z * f1.z + x1.w * f2.y;
            c1 += x1.x * f0.y + x1.y * f1.x + x1.z * f1.w + x1.w * f2.z;
            c2 += x1.x * f0.z + x1.y * f1.y + x1.z * f2.x + x1.w * f2.w;
            reinterpret_cast<uint2*>(g_kh)[(size_t)r0 * 128 + idx] =
                make_uint2(pack_h16(x0.x, x0.y), pack_h16(x0.z, x0.w));
            reinterpret_cast<uint2*>(g_kh)[(size_t)r1 * 128 + idx] =
                make_uint2(pack_h16(x1.x, x1.y), pack_h16(x1.z, x1.w));
        }
        #pragma unroll
        for (int o = 16; o; o >>= 1) {
            a0 += __shfl_down_sync(0xFFFFFFFFu, a0, o);
            a1 += __shfl_down_sync(0xFFFFFFFFu, a1, o);
            a2 += __shfl_down_sync(0xFFFFFFFFu, a2, o);
            c0 += __shfl_down_sync(0xFFFFFFFFu, c0, o);
            c1 += __shfl_down_sync(0xFFFFFFFFu, c1, o);
            c2 += __shfl_down_sync(0xFFFFFFFFu, c2, o);
        }
        if (lane == 0) {
            g_t0[r0] = a0; g_t1[r0] = a1; g_t2[r0] = a2;
            g_t0[r1] = c0; g_t1[r1] = c1; g_t2[r1] = c2;
        }
    } else {
        // W repack, coalesced: thread handles one (d,c) triple.
        int t3 = (bid - 1024) * 256 + tid;        // 0..262143
        int d  = t3 / CH;
        int cc = t3 % CH;
        const float* src = W + (size_t)d * KTOT + cc * 3;
        float w0 = src[0], w1 = src[1], w2 = src[2];
        size_t dst = (size_t)d * KTOT + cc;
        g_Wh[dst]          = __float2half_rn(w0);
        g_Wh[dst + CH]     = __float2half_rn(w1);
        g_Wh[dst + 2 * CH] = __float2half_rn(w2);
    }
}

// ---------------------------------------------------------------------------
// GEMM core: CTA 128x128, 4 warps (2x2), warp tile 64x64, 128 threads.
// Pure fp16 single product, fp32 accumulators. mma.sync is at its HW issue
// ceiling (~287 TF/s) — mainloop is final.
// ---------------------------------------------------------------------------
#define OFF_B       8192
#define CHUNK_BYTES 16384
#define STAGE_BYTES 32768
#define NSTAGE 3
#define SMEM_TOTAL  (NSTAGE * STAGE_BYTES)

struct LdmCtx {
    int tA[4], xA[4];   // per-mi  (16 m-rows each)
    int tB[4], xB[4];   // per-nii (16 n-rows each)
    int kkA, kkB;       // per-lane k-half byte offsets
};

__device__ __forceinline__ LdmCtx make_ctx(int lane, int wm, int wn) {
    LdmCtx c;
    #pragma unroll
    for (int mi = 0; mi < 4; ++mi) {
        int r = wm * 64 + mi * 16 + ((lane >> 3) & 1) * 8 + (lane & 7);
        c.tA[mi] = r * 64;
        c.xA[mi] = ((r >> 1) & 3) << 4;
    }
    #pragma unroll
    for (int nii = 0; nii < 4; ++nii) {
        int r = wn * 64 + nii * 16 + ((lane >> 4) & 1) * 8 + (lane & 7);
        c.tB[nii] = r * 64;
        c.xB[nii] = ((r >> 1) & 3) << 4;
    }
    c.kkA = (lane >> 4) * 16;          // A: matrices 2,3 take k+8 half
    c.kkB = ((lane >> 3) & 1) * 16;    // B: matrices 1,3 take k+8 half
    return c;
}

__device__ __forceinline__ void load_frags(uint32_t st, const LdmCtx& c, int ks,
                                           uint32_t ah[4][4], uint32_t bh[4][4]) {
    const uint32_t base = st + (uint32_t)(ks >> 1) * CHUNK_BYTES;
    const int kbA = (ks & 1) * 32 + c.kkA;
    const int kbB = (ks & 1) * 32 + c.kkB;
    #pragma unroll
    for (int mi = 0; mi < 4; ++mi)
        ldm4(ah[mi][0], ah[mi][1], ah[mi][2], ah[mi][3],
             base + c.tA[mi] + (uint32_t)(kbA ^ c.xA[mi]));
    #pragma unroll
    for (int nii = 0; nii < 4; ++nii)
        ldm4(bh[nii][0], bh[nii][1], bh[nii][2], bh[nii][3],
             base + OFF_B + c.tB[nii] + (uint32_t)(kbB ^ c.xB[nii]));
}

__device__ __forceinline__ void mma_block(float acc[4][8][4],
                                          uint32_t ah[4][4], uint32_t bh[4][4]) {
    #pragma unroll
    for (int mi = 0; mi < 4; ++mi)
        #pragma unroll
        for (int ni = 0; ni < 8; ++ni)
            mma16816(acc[mi][ni], ah[mi][0], ah[mi][1], ah[mi][2], ah[mi][3],
                     bh[ni >> 1][(ni & 1) * 2], bh[ni >> 1][(ni & 1) * 2 + 1]);
}

__device__ __forceinline__ void compute_super(uint32_t st, const LdmCtx& c,
                                              float acc[4][8][4]) {
    uint32_t a0[4][4], b0[4][4], a1[4][4], b1[4][4];
    load_frags(st, c, 0, a0, b0);
    load_frags(st, c, 1, a1, b1);
    mma_block(acc, a0, b0);
    load_frags(st, c, 2, a0, b0);
    mma_block(acc, a1, b1);
    load_frags(st, c, 3, a1, b1);
    mma_block(acc, a0, b0);
    mma_block(acc, a1, b1);
}

// ---------------------------------------------------------------------------
// Stage A: U[b][j][d] = sum_{w,c} k[b][j+w-1][c] * Wop[d][w*CH+c]
// Single wave (256 CTAs <= 296 slots) — unchanged, at mma issue floor.
// ---------------------------------------------------------------------------
__device__ __forceinline__ void loadA_chunk(uint32_t sbase, int b, int jt, int dt,
                                            int ch, int tid) {
    const int w  = ch >> 4;
    const int c0 = (ch & 15) * 32;
    #pragma unroll
    for (int u = 0; u < 4; ++u) {
        int f = tid + u * 128;             // 0..511
        int row = f >> 2, c16 = f & 3;
        uint32_t so = sw_off(row, c16 * 16);
        int jg = jt + row + w - 1;
        int ok = (jg >= 0 && jg < LK) ? 16 : 0;
        int jc = (jg >= 0 && jg < LK) ? jg : 0;
        size_t gi = ((size_t)b * LK + jc) * CH + c0 + c16 * 8;
        cpa16(sbase + so, g_kh + gi, ok);
        size_t wi = (size_t)(dt + row) * KTOT + w * CH + c0 + c16 * 8;
        cpa16(sbase + OFF_B + so, g_Wh + wi, 16);
    }
}

__device__ __forceinline__ void loadA_super(uint32_t sbase, int b, int jt, int dt,
                                            int sc, int tid) {
    loadA_chunk(sbase,               b, jt, dt, 2 * sc,     tid);
    loadA_chunk(sbase + CHUNK_BYTES, b, jt, dt, 2 * sc + 1, tid);
}

__global__ __launch_bounds__(128, 2) void gemmA_mma() {
    extern __shared__ __align__(16) uint8_t smem[];
    const int b  = blockIdx.z;
    const int jt = blockIdx.y * 128;
    const int dt = blockIdx.x * 128;
    const int tid = threadIdx.x, lane = tid & 31, wid = tid >> 5;
    const int wm = wid >> 1, wn = wid & 1;
    const int g = lane >> 2, t = lane & 3;
    const uint32_t sb = smem_u32(smem);
    const LdmCtx ctx = make_ctx(lane, wm, wn);

    float acc[4][8][4];
    #pragma unroll
    for (int a = 0; a < 4; ++a)
        #pragma unroll
        for (int bq = 0; bq < 8; ++bq)
            #pragma unroll
            for (int c = 0; c < 4; ++c) acc[a][bq][c] = 0.f;

    loadA_super(sb,               b, jt, dt, 0, tid); CP_COMMIT();
    loadA_super(sb + STAGE_BYTES, b, jt, dt, 1, tid); CP_COMMIT();
    for (int sc = 0; sc < 24; ++sc) {
        CP_WAIT1();
        __syncthreads();
        if (sc + 2 < 24)
            loadA_super(sb + (uint32_t)((sc + 2) % NSTAGE) * STAGE_BYTES, b, jt, dt, sc + 2, tid);
        CP_COMMIT();
        compute_super(sb + (uint32_t)(sc % NSTAGE) * STAGE_BYTES, ctx, acc);
    }

    // epilogue: store U as fp16
    #pragma unroll
    for (int mi = 0; mi < 4; ++mi) {
        #pragma unroll
        for (int ni = 0; ni < 8; ++ni) {
            int j0 = jt + wm * 64 + mi * 16 + g;
            int d0 = dt + wn * 64 + ni * 8 + 2 * t;
            #pragma unroll
            for (int rr = 0; rr < 2; ++rr) {
                uint32_t hp = pack_h16(acc[mi][ni][rr * 2 + 0], acc[mi][ni][rr * 2 + 1]);
                size_t o = ((size_t)b * LK + (j0 + rr * 8)) * DIM + d0;
                *reinterpret_cast<uint32_t*>(g_Uh + o) = hp;
            }
        }
    }
}

// ---------------------------------------------------------------------------
// Stage B (PERSISTENT): out = q·U^T + qb + bbj + bias_b
// 296 CTAs (exactly 2/SM), tiles pulled from an atomic counter -> no wave
// quantization tail (512 tiles / 296 slots was 1.73 waves).
// Tile decode keeps consecutive tiles in same (b, it) for q-row L2 reuse.
// ---------------------------------------------------------------------------
#define NTILES_B 512
#define GRID_B   296

__device__ __forceinline__ void loadB_chunk(uint32_t sbase, int b, int it, int jt,
                                            int ch, int tid) {
    const int kt = ch * 32;
    #pragma unroll
    for (int u = 0; u < 4; ++u) {
        int f = tid + u * 128;
        int row = f >> 2, c16 = f & 3;
        uint32_t so = sw_off(row, c16 * 16);
        size_t qi = ((size_t)b * LQ + it + row) * DIM + kt + c16 * 8;
        cpa16(sbase + so, g_qh + qi, 16);
        size_t ui = ((size_t)b * LK + jt + row) * DIM + kt + c16 * 8;
        cpa16(sbase + OFF_B + so, g_Uh + ui, 16);
    }
}

__device__ __forceinline__ void loadB_super(uint32_t sbase, int b, int it, int jt,
                                            int sc, int tid) {
    loadB_chunk(sbase,               b, it, jt, 2 * sc,     tid);
    loadB_chunk(sbase + CHUNK_BYTES, b, it, jt, 2 * sc + 1, tid);
}

__global__ __launch_bounds__(128, 2) void gemmB_mma(const float* __restrict__ biasb,
                                                    float* __restrict__ out) {
    extern __shared__ __align__(16) uint8_t smem[];
    __shared__ unsigned int s_tile;
    const int tid = threadIdx.x, lane = tid & 31, wid = tid >> 5;
    const int wm = wid >> 1, wn = wid & 1;
    const int g = lane >> 2, t = lane & 3;
    const uint32_t sb = smem_u32(smem);
    const LdmCtx ctx = make_ctx(lane, wm, wn);
    const float bB = biasb[0];

    for (;;) {
        if (tid == 0) s_tile = atomicAdd(&g_tileCtr, 1u);
        __syncthreads();
        unsigned int tile = s_tile;
        if (tile >= NTILES_B) break;
        const int b  = tile >> 6;
        const int it = ((tile >> 3) & 7) * 128;
        const int jt = (tile & 7) * 128;

        float acc[4][8][4];
        #pragma unroll
        for (int a = 0; a < 4; ++a)
            #pragma unroll
            for (int bq = 0; bq < 8; ++bq)
                #pragma unroll
                for (int c = 0; c < 4; ++c) acc[a][bq][c] = 0.f;

        loadB_super(sb,               b, it, jt, 0, tid); CP_COMMIT();
        loadB_super(sb + STAGE_BYTES, b, it, jt, 1, tid); CP_COMMIT();
        for (int sc = 0; sc < 8; ++sc) {
            CP_WAIT1();
            __syncthreads();
            if (sc + 2 < 8)
                loadB_super(sb + (uint32_t)((sc + 2) % NSTAGE) * STAGE_BYTES, b, it, jt, sc + 2, tid);
            CP_COMMIT();
            compute_super(sb + (uint32_t)(sc % NSTAGE) * STAGE_BYTES, ctx, acc);
        }
        CP_WAIT0();   // drain before ring reuse next tile

        // bbj inline: bbj[b,j] = t0[b,j-1] + t1[b,j] + t2[b,j+1] (edges clipped)
        float bbv[8][2];
        #pragma unroll
        for (int ni = 0; ni < 8; ++ni) {
            #pragma unroll
            for (int jj = 0; jj < 2; ++jj) {
                int j = jt + wn * 64 + ni * 8 + 2 * t + jj;   // 0..1023
                int idx = b * LK + j;
                float s = g_t1[idx];
                if (j > 0)      s += g_t0[idx - 1];
                if (j < LK - 1) s += g_t2[idx + 1];
                bbv[ni][jj] = s;
            }
        }

        #pragma unroll
        for (int mi = 0; mi < 4; ++mi) {
            int i0 = it + wm * 64 + mi * 16 + g;
            float cb0 = g_qb[b * LQ + i0] + bB;
            float cb1 = g_qb[b * LQ + i0 + 8] + bB;
            #pragma unroll
            for (int ni = 0; ni < 8; ++ni) {
                int j0 = jt + wn * 64 + ni * 8 + 2 * t;
                float2 r0 = make_float2(acc[mi][ni][0] + cb0 + bbv[ni][0],
                                        acc[mi][ni][1] + cb0 + bbv[ni][1]);
                float2 r1 = make_float2(acc[mi][ni][2] + cb1 + bbv[ni][0],
                                        acc[mi][ni][3] + cb1 + bbv[ni][1]);
                *reinterpret_cast<float2*>(out + ((size_t)b * LQ + i0) * LK + j0)     = r0;
                *reinterpret_cast<float2*>(out + ((size_t)b * LQ + i0 + 8) * LK + j0) = r1;
            }
        }
        __syncthreads();   // all reads of smem/s_tile done before next tile
    }
}

// ---------------------------------------------------------------------------
extern "C" void kernel_launch(void* const* d_in, const int* in_sizes, int n_in,
                              void* d_out, int out_size) {
    const float* q     = (const float*)d_in[0];   // (8,1024,512)
    const float* k     = (const float*)d_in[1];   // (8,1024,512)
    const float* W     = (const float*)d_in[2];   // (512,1536)
    const float* bk    = (const float*)d_in[3];   // (1536,)
    const float* Wb    = (const float*)d_in[4];   // (512,1)
    const float* bb    = (const float*)d_in[5];   // (1,)
    const float* biasb = (const float*)d_in[6];   // (1,)
    float* out = (float*)d_out;                   // (8,1024,1024)

    // idempotent, deterministic — no static guard
    cudaFuncSetAttribute(gemmA_mma, cudaFuncAttributeMaxDynamicSharedMemorySize, SMEM_TOTAL);
    cudaFuncSetAttribute(gemmB_mma, cudaFuncAttributeMaxDynamicSharedMemorySize, SMEM_TOTAL);

    // fused preamble (also resets the gemmB tile counter)
    preamble_kernel<<<2048, 256>>>(q, k, W, bk, Wb, bb);

    dim3 gA(DIM / 128, LK / 128, BATCH);          // (4, 8, 8) — single wave
    gemmA_mma<<<gA, 128, SMEM_TOTAL>>>();

    gemmB_mma<<<GRID_B, 128, SMEM_TOTAL>>>(biasb, out);   // persistent
}

// round 16
// speedup vs baseline: 1.5773x; 1.5773x over previous
#include <cuda_runtime.h>
#include <cuda_fp16.h>
#include <cstdint>

// Problem shapes (fixed by the dataset)
#define BATCH 8
#define LQ    1024
#define LK    1024
#define DIM   512
#define CH    512
#define KTOT  1536   // 3*CH

// ---------------------------------------------------------------------------
// Scratch (device globals). Referenced ONLY from device code (host-side
// &g_xxx yields the shadow symbol: the round-3/4 bug).
// ---------------------------------------------------------------------------
__device__ __half g_qh[BATCH * LQ * DIM];
__device__ __half g_kh[BATCH * LK * CH];
__device__ __half g_Wh[DIM * KTOT];              // Wop[d][w*CH+c] = W[d, c*3+w]
__device__ __half g_Uh[BATCH * LK * DIM];
__device__ float g_qb[BATCH * LQ];
__device__ float g_t0[BATCH * LK];               // per-row dots for bbj conv
__device__ float g_t1[BATCH * LK];
__device__ float g_t2[BATCH * LK];

// ---------------------------------------------------------------------------
// PTX helpers
// ---------------------------------------------------------------------------
__device__ __forceinline__ void mma16816(float* c,
                                         uint32_t a0, uint32_t a1, uint32_t a2, uint32_t a3,
                                         uint32_t b0, uint32_t b1) {
    asm volatile(
        "mma.sync.aligned.m16n8k16.row.col.f32.f16.f16.f32 "
        "{%0,%1,%2,%3}, {%4,%5,%6,%7}, {%8,%9}, {%0,%1,%2,%3};"
        : "+f"(c[0]), "+f"(c[1]), "+f"(c[2]), "+f"(c[3])
        : "r"(a0), "r"(a1), "r"(a2), "r"(a3), "r"(b0), "r"(b1));
}

__device__ __forceinline__ void ldm4(uint32_t& r0, uint32_t& r1, uint32_t& r2, uint32_t& r3,
                                     uint32_t a) {
    asm volatile("ldmatrix.sync.aligned.m8n8.x4.shared.b16 {%0,%1,%2,%3}, [%4];"
                 : "=r"(r0), "=r"(r1), "=r"(r2), "=r"(r3) : "r"(a));
}

__device__ __forceinline__ uint32_t smem_u32(const void* p) {
    uint32_t a;
    asm("{ .reg .u64 t; cvta.to.shared.u64 t, %1; cvt.u32.u64 %0, t; }" : "=r"(a) : "l"(p));
    return a;
}

__device__ __forceinline__ void cpa16(uint32_t dst, const void* src, int srcsz) {
    asm volatile("cp.async.cg.shared.global [%0], [%1], 16, %2;"
                 :: "r"(dst), "l"(src), "r"(srcsz) : "memory");
}
#define CP_COMMIT() asm volatile("cp.async.commit_group;" ::: "memory")
#define CP_WAIT1()  asm volatile("cp.async.wait_group 1;" ::: "memory")

// smem tile: 128 rows x 64 bytes (32 fp16), XOR-swizzled:
//   phys = row*64 + (kb ^ (((row>>1)&3)<<4))
__device__ __forceinline__ uint32_t sw_off(int row, int kb) {
    return (uint32_t)(row * 64 + (kb ^ (((row >> 1) & 3) << 4)));
}

__device__ __forceinline__ uint32_t pack_h16(float a, float b) {
    return (uint32_t)__half_as_ushort(__float2half_rn(a)) |
           ((uint32_t)__half_as_ushort(__float2half_rn(b)) << 16);
}

// ---------------------------------------------------------------------------
// Fused preamble (measured-best form): 2 rows per warp in q/k paths,
// coalesced W repack.
//   blocks [0,512):     q -> fp16 + qb row dots
//   blocks [512,1024):  k -> fp16 + t0/t1/t2 row dots
//   blocks [1024,2048): W repack -> fp16 (thread per (d,c) triple)
// ---------------------------------------------------------------------------
__global__ void preamble_kernel(const float* __restrict__ q,
                                const float* __restrict__ k,
                                const float* __restrict__ W,
                                const float* __restrict__ bk,
                                const float* __restrict__ Wb,
                                const float* __restrict__ bb) {
    int bid = blockIdx.x;
    int tid = threadIdx.x;
    if (bid < 512) {
        int wpair = (bid * 256 + tid) >> 5;         // 0..4095 -> rows 2w, 2w+1
        int lane  = tid & 31;
        int r0 = 2 * wpair, r1 = r0 + 1;
        const float4* q0  = reinterpret_cast<const float4*>(q) + (size_t)r0 * 128;
        const float4* q1  = reinterpret_cast<const float4*>(q) + (size_t)r1 * 128;
        const float4* wb4 = reinterpret_cast<const float4*>(Wb);
        float s0 = 0.f, s1 = 0.f;
        #pragma unroll
        for (int v = 0; v < 4; ++v) {
            int idx = lane + 32 * v;
            float4 x0 = q0[idx];
            float4 x1 = q1[idx];
            float4 wv = wb4[idx];
            s0 += x0.x * wv.x + x0.y * wv.y + x0.z * wv.z + x0.w * wv.w;
            s1 += x1.x * wv.x + x1.y * wv.y + x1.z * wv.z + x1.w * wv.w;
            reinterpret_cast<uint2*>(g_qh)[(size_t)r0 * 128 + idx] =
                make_uint2(pack_h16(x0.x, x0.y), pack_h16(x0.z, x0.w));
            reinterpret_cast<uint2*>(g_qh)[(size_t)r1 * 128 + idx] =
                make_uint2(pack_h16(x1.x, x1.y), pack_h16(x1.z, x1.w));
        }
        #pragma unroll
        for (int o = 16; o; o >>= 1) {
            s0 += __shfl_down_sync(0xFFFFFFFFu, s0, o);
            s1 += __shfl_down_sync(0xFFFFFFFFu, s1, o);
        }
        if (lane == 0) {
            float b0v = bb[0];
            g_qb[r0] = s0 + b0v;
            g_qb[r1] = s1 + b0v;
        }
    } else if (bid < 1024) {
        int wpair = ((bid - 512) * 256 + tid) >> 5;
        int lane  = tid & 31;
        int r0 = 2 * wpair, r1 = r0 + 1;
        const float4* k0  = reinterpret_cast<const float4*>(k) + (size_t)r0 * 128;
        const float4* k1  = reinterpret_cast<const float4*>(k) + (size_t)r1 * 128;
        const float4* bk4 = reinterpret_cast<const float4*>(bk);
        float a0 = 0.f, a1 = 0.f, a2 = 0.f;      // row r0 dots
        float c0 = 0.f, c1 = 0.f, c2 = 0.f;      // row r1 dots
        #pragma unroll
        for (int v = 0; v < 4; ++v) {
            int idx = lane + 32 * v;              // float4 slot; c0 = 4*idx
            float4 x0 = k0[idx];
            float4 x1 = k1[idx];
            float4 f0 = bk4[3 * idx + 0];
            float4 f1 = bk4[3 * idx + 1];
            float4 f2 = bk4[3 * idx + 2];
            a0 += x0.x * f0.x + x0.y * f0.w + x0.z * f1.z + x0.w * f2.y;
            a1 += x0.x * f0.y + x0.y * f1.x + x0.z * f1.w + x0.w * f2.z;
            a2 += x0.x * f0.z + x0.y * f1.y + x0.z * f2.x + x0.w * f2.w;
            c0 += x1.x * f0.x + x1.y * f0.w + x1.z * f1.z + x1.w * f2.y;
            c1 += x1.x * f0.y + x1.y * f1.x + x1.z * f1.w + x1.w * f2.z;
            c2 += x1.x * f0.z + x1.y * f1.y + x1.z * f2.x + x1.w * f2.w;
            reinterpret_cast<uint2*>(g_kh)[(size_t)r0 * 128 + idx] =
                make_uint2(pack_h16(x0.x, x0.y), pack_h16(x0.z, x0.w));
            reinterpret_cast<uint2*>(g_kh)[(size_t)r1 * 128 + idx] =
                make_uint2(pack_h16(x1.x, x1.y), pack_h16(x1.z, x1.w));
        }
        #pragma unroll
        for (int o = 16; o; o >>= 1) {
            a0 += __shfl_down_sync(0xFFFFFFFFu, a0, o);
            a1 += __shfl_down_sync(0xFFFFFFFFu, a1, o);
            a2 += __shfl_down_sync(0xFFFFFFFFu, a2, o);
            c0 += __shfl_down_sync(0xFFFFFFFFu, c0, o);
            c1 += __shfl_down_sync(0xFFFFFFFFu, c1, o);
            c2 += __shfl_down_sync(0xFFFFFFFFu, c2, o);
        }
        if (lane == 0) {
            g_t0[r0] = a0; g_t1[r0] = a1; g_t2[r0] = a2;
            g_t0[r1] = c0; g_t1[r1] = c1; g_t2[r1] = c2;
        }
    } else {
        // W repack, coalesced: thread handles one (d,c) triple.
        int t3 = (bid - 1024) * 256 + tid;        // 0..262143
        int d  = t3 / CH;
        int cc = t3 % CH;
        const float* src = W + (size_t)d * KTOT + cc * 3;
        float w0 = src[0], w1 = src[1], w2 = src[2];
        size_t dst = (size_t)d * KTOT + cc;
        g_Wh[dst]          = __float2half_rn(w0);
        g_Wh[dst + CH]     = __float2half_rn(w1);
        g_Wh[dst + 2 * CH] = __float2half_rn(w2);
    }
}

// ---------------------------------------------------------------------------
// GEMM core: CTA 128x128, 4 warps (2x2), warp tile 64x64, 128 threads.
// Pure fp16 single product, fp32 accumulators. mma.sync runs at its HW issue
// ceiling (~287 TF/s measured) — mainloop is final.
// ---------------------------------------------------------------------------
#define OFF_B       8192
#define CHUNK_BYTES 16384
#define STAGE_BYTES 32768
#define NSTAGE 3
#define SMEM_TOTAL  (NSTAGE * STAGE_BYTES)

struct LdmCtx {
    int tA[4], xA[4];   // per-mi  (16 m-rows each)
    int tB[4], xB[4];   // per-nii (16 n-rows each)
    int kkA, kkB;       // per-lane k-half byte offsets
};

__device__ __forceinline__ LdmCtx make_ctx(int lane, int wm, int wn) {
    LdmCtx c;
    #pragma unroll
    for (int mi = 0; mi < 4; ++mi) {
        int r = wm * 64 + mi * 16 + ((lane >> 3) & 1) * 8 + (lane & 7);
        c.tA[mi] = r * 64;
        c.xA[mi] = ((r >> 1) & 3) << 4;
    }
    #pragma unroll
    for (int nii = 0; nii < 4; ++nii) {
        int r = wn * 64 + nii * 16 + ((lane >> 4) & 1) * 8 + (lane & 7);
        c.tB[nii] = r * 64;
        c.xB[nii] = ((r >> 1) & 3) << 4;
    }
    c.kkA = (lane >> 4) * 16;          // A: matrices 2,3 take k+8 half
    c.kkB = ((lane >> 3) & 1) * 16;    // B: matrices 1,3 take k+8 half
    return c;
}

__device__ __forceinline__ void load_frags(uint32_t st, const LdmCtx& c, int ks,
                                           uint32_t ah[4][4], uint32_t bh[4][4]) {
    const uint32_t base = st + (uint32_t)(ks >> 1) * CHUNK_BYTES;
    const int kbA = (ks & 1) * 32 + c.kkA;
    const int kbB = (ks & 1) * 32 + c.kkB;
    #pragma unroll
    for (int mi = 0; mi < 4; ++mi)
        ldm4(ah[mi][0], ah[mi][1], ah[mi][2], ah[mi][3],
             base + c.tA[mi] + (uint32_t)(kbA ^ c.xA[mi]));
    #pragma unroll
    for (int nii = 0; nii < 4; ++nii)
        ldm4(bh[nii][0], bh[nii][1], bh[nii][2], bh[nii][3],
             base + OFF_B + c.tB[nii] + (uint32_t)(kbB ^ c.xB[nii]));
}

__device__ __forceinline__ void mma_block(float acc[4][8][4],
                                          uint32_t ah[4][4], uint32_t bh[4][4]) {
    #pragma unroll
    for (int mi = 0; mi < 4; ++mi)
        #pragma unroll
        for (int ni = 0; ni < 8; ++ni)
            mma16816(acc[mi][ni], ah[mi][0], ah[mi][1], ah[mi][2], ah[mi][3],
                     bh[ni >> 1][(ni & 1) * 2], bh[ni >> 1][(ni & 1) * 2 + 1]);
}

__device__ __forceinline__ void compute_super(uint32_t st, const LdmCtx& c,
                                              float acc[4][8][4]) {
    uint32_t a0[4][4], b0[4][4], a1[4][4], b1[4][4];
    load_frags(st, c, 0, a0, b0);
    load_frags(st, c, 1, a1, b1);
    mma_block(acc, a0, b0);
    load_frags(st, c, 2, a0, b0);
    mma_block(acc, a1, b1);
    load_frags(st, c, 3, a1, b1);
    mma_block(acc, a0, b0);
    mma_block(acc, a1, b1);
}

// ---------------------------------------------------------------------------
// Stage A: U[b][j][d] = sum_{w,c} k[b][j+w-1][c] * Wop[d][w*CH+c]
// Single wave (256 CTAs <= 296 slots), at the mma issue floor.
// ---------------------------------------------------------------------------
__device__ __forceinline__ void loadA_chunk(uint32_t sbase, int b, int jt, int dt,
                                            int ch, int tid) {
    const int w  = ch >> 4;
    const int c0 = (ch & 15) * 32;
    #pragma unroll
    for (int u = 0; u < 4; ++u) {
        int f = tid + u * 128;             // 0..511
        int row = f >> 2, c16 = f & 3;
        uint32_t so = sw_off(row, c16 * 16);
        int jg = jt + row + w - 1;
        int ok = (jg >= 0 && jg < LK) ? 16 : 0;
        int jc = (jg >= 0 && jg < LK) ? jg : 0;
        size_t gi = ((size_t)b * LK + jc) * CH + c0 + c16 * 8;
        cpa16(sbase + so, g_kh + gi, ok);
        size_t wi = (size_t)(dt + row) * KTOT + w * CH + c0 + c16 * 8;
        cpa16(sbase + OFF_B + so, g_Wh + wi, 16);
    }
}

__device__ __forceinline__ void loadA_super(uint32_t sbase, int b, int jt, int dt,
                                            int sc, int tid) {
    loadA_chunk(sbase,               b, jt, dt, 2 * sc,     tid);
    loadA_chunk(sbase + CHUNK_BYTES, b, jt, dt, 2 * sc + 1, tid);
}

__global__ __launch_bounds__(128, 2) void gemmA_mma() {
    extern __shared__ __align__(16) uint8_t smem[];
    const int b  = blockIdx.z;
    const int jt = blockIdx.y * 128;
    const int dt = blockIdx.x * 128;
    const int tid = threadIdx.x, lane = tid & 31, wid = tid >> 5;
    const int wm = wid >> 1, wn = wid & 1;
    const int g = lane >> 2, t = lane & 3;
    const uint32_t sb = smem_u32(smem);
    const LdmCtx ctx = make_ctx(lane, wm, wn);

    float acc[4][8][4];
    #pragma unroll
    for (int a = 0; a < 4; ++a)
        #pragma unroll
        for (int bq = 0; bq < 8; ++bq)
            #pragma unroll
            for (int c = 0; c < 4; ++c) acc[a][bq][c] = 0.f;

    loadA_super(sb,               b, jt, dt, 0, tid); CP_COMMIT();
    loadA_super(sb + STAGE_BYTES, b, jt, dt, 1, tid); CP_COMMIT();
    for (int sc = 0; sc < 24; ++sc) {
        CP_WAIT1();
        __syncthreads();
        if (sc + 2 < 24)
            loadA_super(sb + (uint32_t)((sc + 2) % NSTAGE) * STAGE_BYTES, b, jt, dt, sc + 2, tid);
        CP_COMMIT();
        compute_super(sb + (uint32_t)(sc % NSTAGE) * STAGE_BYTES, ctx, acc);
    }

    // epilogue: store U as fp16
    #pragma unroll
    for (int mi = 0; mi < 4; ++mi) {
        #pragma unroll
        for (int ni = 0; ni < 8; ++ni) {
            int j0 = jt + wm * 64 + mi * 16 + g;
            int d0 = dt + wn * 64 + ni * 8 + 2 * t;
            #pragma unroll
            for (int rr = 0; rr < 2; ++rr) {
                uint32_t hp = pack_h16(acc[mi][ni][rr * 2 + 0], acc[mi][ni][rr * 2 + 1]);
                size_t o = ((size_t)b * LK + (j0 + rr * 8)) * DIM + d0;
                *reinterpret_cast<uint32_t*>(g_Uh + o) = hp;
            }
        }
    }
}

// ---------------------------------------------------------------------------
// Stage B: out[b][i][j] = q[b][i][:] . U[b][j][:] + qb[b,i] + bbj[b,j] + bias_b
// ---------------------------------------------------------------------------
__device__ __forceinline__ void loadB_chunk(uint32_t sbase, int b, int it, int jt,
                                            int ch, int tid) {
    const int kt = ch * 32;
    #pragma unroll
    for (int u = 0; u < 4; ++u) {
        int f = tid + u * 128;
        int row = f >> 2, c16 = f & 3;
        uint32_t so = sw_off(row, c16 * 16);
        size_t qi = ((size_t)b * LQ + it + row) * DIM + kt + c16 * 8;
        cpa16(sbase + so, g_qh + qi, 16);
        size_t ui = ((size_t)b * LK + jt + row) * DIM + kt + c16 * 8;
        cpa16(sbase + OFF_B + so, g_Uh + ui, 16);
    }
}

__device__ __forceinline__ void loadB_super(uint32_t sbase, int b, int it, int jt,
                                            int sc, int tid) {
    loadB_chunk(sbase,               b, it, jt, 2 * sc,     tid);
    loadB_chunk(sbase + CHUNK_BYTES, b, it, jt, 2 * sc + 1, tid);
}

__global__ __launch_bounds__(128, 2) void gemmB_mma(const float* __restrict__ biasb,
                                                    float* __restrict__ out) {
    extern __shared__ __align__(16) uint8_t smem[];
    const int b  = blockIdx.z;
    const int it = blockIdx.y * 128;
    const int jt = blockIdx.x * 128;
    const int tid = threadIdx.x, lane = tid & 31, wid = tid >> 5;
    const int wm = wid >> 1, wn = wid & 1;
    const int g = lane >> 2, t = lane & 3;
    const uint32_t sb = smem_u32(smem);
    const LdmCtx ctx = make_ctx(lane, wm, wn);

    float acc[4][8][4];
    #pragma unroll
    for (int a = 0; a < 4; ++a)
        #pragma unroll
        for (int bq = 0; bq < 8; ++bq)
            #pragma unroll
            for (int c = 0; c < 4; ++c) acc[a][bq][c] = 0.f;

    loadB_super(sb,               b, it, jt, 0, tid); CP_COMMIT();
    loadB_super(sb + STAGE_BYTES, b, it, jt, 1, tid); CP_COMMIT();
    for (int sc = 0; sc < 8; ++sc) {
        CP_WAIT1();
        __syncthreads();
        if (sc + 2 < 8)
            loadB_super(sb + (uint32_t)((sc + 2) % NSTAGE) * STAGE_BYTES, b, it, jt, sc + 2, tid);
        CP_COMMIT();
        compute_super(sb + (uint32_t)(sc % NSTAGE) * STAGE_BYTES, ctx, acc);
    }

    // bbj inline: bbj[b,j] = t0[b,j-1] + t1[b,j] + t2[b,j+1] (edges clipped)
    float bbv[8][2];
    #pragma unroll
    for (int ni = 0; ni < 8; ++ni) {
        #pragma unroll
        for (int jj = 0; jj < 2; ++jj) {
            int j = jt + wn * 64 + ni * 8 + 2 * t + jj;   // 0..1023
            int idx = b * LK + j;
            float s = g_t1[idx];
            if (j > 0)      s += g_t0[idx - 1];
            if (j < LK - 1) s += g_t2[idx + 1];
            bbv[ni][jj] = s;
        }
    }

    const float bB = biasb[0];
    #pragma unroll
    for (int mi = 0; mi < 4; ++mi) {
        int i0 = it + wm * 64 + mi * 16 + g;
        float cb0 = g_qb[b * LQ + i0] + bB;
        float cb1 = g_qb[b * LQ + i0 + 8] + bB;
        #pragma unroll
        for (int ni = 0; ni < 8; ++ni) {
            int j0 = jt + wn * 64 + ni * 8 + 2 * t;
            float2 r0 = make_float2(acc[mi][ni][0] + cb0 + bbv[ni][0],
                                    acc[mi][ni][1] + cb0 + bbv[ni][1]);
            float2 r1 = make_float2(acc[mi][ni][2] + cb1 + bbv[ni][0],
                                    acc[mi][ni][3] + cb1 + bbv[ni][1]);
            *reinterpret_cast<float2*>(out + ((size_t)b * LQ + i0) * LK + j0)     = r0;
            *reinterpret_cast<float2*>(out + ((size_t)b * LQ + i0 + 8) * LK + j0) = r1;
        }
    }
}

// ---------------------------------------------------------------------------
extern "C" void kernel_launch(void* const* d_in, const int* in_sizes, int n_in,
                              void* d_out, int out_size) {
    const float* q     = (const float*)d_in[0];   // (8,1024,512)
    const float* k     = (const float*)d_in[1];   // (8,1024,512)
    const float* W     = (const float*)d_in[2];   // (512,1536)
    const float* bk    = (const float*)d_in[3];   // (1536,)
    const float* Wb    = (const float*)d_in[4];   // (512,1)
    const float* bb    = (const float*)d_in[5];   // (1,)
    const float* biasb = (const float*)d_in[6];   // (1,)
    float* out = (float*)d_out;                   // (8,1024,1024)

    // idempotent, deterministic — no static guard
    cudaFuncSetAttribute(gemmA_mma, cudaFuncAttributeMaxDynamicSharedMemorySize, SMEM_TOTAL);
    cudaFuncSetAttribute(gemmB_mma, cudaFuncAttributeMaxDynamicSharedMemorySize, SMEM_TOTAL);

    // fused single-launch preamble, 2 rows/warp
    preamble_kernel<<<2048, 256>>>(q, k, W, bk, Wb, bb);

    dim3 gA(DIM / 128, LK / 128, BATCH);          // (4, 8, 8)
    gemmA_mma<<<gA, 128, SMEM_TOTAL>>>();

    dim3 gB(LK / 128, LQ / 128, BATCH);           // (8, 8, 8)
    gemmB_mma<<<gB, 128, SMEM_TOTAL>>>(biasb, out);
}